// round 9
// baseline (speedup 1.0000x reference)
#include <cuda_runtime.h>
#include <cuda_fp16.h>
#include <cstdint>

#define N_TOK 4096
#define NH 8
#define DH 16
#define DM 128
#define NSPLIT 4
// (1/sqrt(128)) * log2(e): softmax in exp2 domain
#define QSCL 0.12751743f

// fp16 scratch written by projection
__device__ __half g_qT[NH * N_TOK * DH];   // [head][tok][d]  (q, pre-scaled)
__device__ __half g_kT[NH * N_TOK * DH];   // [head][tok][d]
__device__ __half g_v [NH * DH * N_TOK];   // [head*16+d][tok]
// split-KV partials
__device__ float g_pnum[NSPLIT][NH][DH][N_TOK];   // 8 MB
__device__ float g_pden[NSPLIT][NH][N_TOK];       // 512 KB

// ---------------- helpers ----------------
__device__ __forceinline__ unsigned long long pack2(float lo, float hi) {
    unsigned long long r;
    asm("mov.b64 %0, {%1, %2};" : "=l"(r) : "f"(lo), "f"(hi));
    return r;
}
__device__ __forceinline__ float2 unpack2(unsigned long long v) {
    float2 f;
    asm("mov.b64 {%0, %1}, %2;" : "=f"(f.x), "=f"(f.y) : "l"(v));
    return f;
}
__device__ __forceinline__ unsigned long long ffma2(unsigned long long a,
                                                    unsigned long long b,
                                                    unsigned long long c) {
    unsigned long long d;
    asm("fma.rn.f32x2 %0, %1, %2, %3;" : "=l"(d) : "l"(a), "l"(b), "l"(c));
    return d;
}
__device__ __forceinline__ uint32_t cvt_h2(float hi, float lo) {
    uint32_t d;
    asm("cvt.rn.f16x2.f32 %0, %1, %2;" : "=r"(d) : "f"(hi), "f"(lo));
    return d;
}
__device__ __forceinline__ uint32_t ex2_h2(uint32_t a) {
    uint32_t d;
    asm("ex2.approx.f16x2 %0, %1;" : "=r"(d) : "r"(a));
    return d;
}
__device__ __forceinline__ void hmma(float& c0, float& c1, float& c2, float& c3,
                                     uint32_t a0, uint32_t a1, uint32_t a2, uint32_t a3,
                                     uint32_t b0, uint32_t b1) {
    asm volatile("mma.sync.aligned.m16n8k16.row.col.f32.f16.f16.f32 "
                 "{%0,%1,%2,%3}, {%4,%5,%6,%7}, {%8,%9}, {%0,%1,%2,%3};"
                 : "+f"(c0), "+f"(c1), "+f"(c2), "+f"(c3)
                 : "r"(a0), "r"(a1), "r"(a2), "r"(a3), "r"(b0), "r"(b1));
}

// ---------------- Kernel 1: QKV projection v4 (1024 CTAs) ----------------
// grid (32, 32): bx = 128-token block, by = 12-row group (48 rows/head = 4 groups).
// 128 threads, 1 token each; x double-buffered in registers (8-c blocks).
__global__ void __launch_bounds__(128) qkv_proj_kernel(const float* __restrict__ x,
                                                       const float* __restrict__ W) {
    __shared__ __align__(16) float Wsh[DM * 12];    // [c][o], 6 KB
    const int head = blockIdx.y >> 2;
    const int part = blockIdx.y & 3;                // 12-row slice within head
    const int tid  = threadIdx.x;
    const int n    = blockIdx.x * 128 + tid;

    for (int i = tid; i < 12 * DM; i += 128) {
        int o = i / DM, c = i % DM;                 // o 0..11
        float wv = W[(head * 48 + part * 12 + o) * DM + c];
        if (part * 12 + o < 16) wv *= QSCL;         // q rows
        Wsh[c * 12 + o] = wv;
    }
    __syncthreads();

    unsigned long long a[6];
#pragma unroll
    for (int j = 0; j < 6; ++j) a[j] = 0ULL;

    const float* xp = x + n;
    float xb[2][8];
#pragma unroll
    for (int i = 0; i < 8; ++i) xb[0][i] = xp[i * N_TOK];

#pragma unroll 2
    for (int blk = 0; blk < 16; ++blk) {
        const int cur = blk & 1;
        if (blk < 15) {
#pragma unroll
            for (int i = 0; i < 8; ++i)
                xb[cur ^ 1][i] = xp[((blk + 1) * 8 + i) * N_TOK];
        }
#pragma unroll
        for (int i = 0; i < 8; ++i) {
            const int c = blk * 8 + i;
            unsigned long long xx = pack2(xb[cur][i], xb[cur][i]);
            const ulonglong2* wr = reinterpret_cast<const ulonglong2*>(&Wsh[c * 12]);
            ulonglong2 w01 = wr[0];
            ulonglong2 w23 = wr[1];
            ulonglong2 w45 = wr[2];
            a[0] = ffma2(xx, w01.x, a[0]);
            a[1] = ffma2(xx, w01.y, a[1]);
            a[2] = ffma2(xx, w23.x, a[2]);
            a[3] = ffma2(xx, w23.y, a[3]);
            a[4] = ffma2(xx, w45.x, a[4]);
            a[5] = ffma2(xx, w45.y, a[5]);
        }
    }

    auto h2of = [](unsigned long long v) {
        float2 f = unpack2(v);
        return cvt_h2(f.y, f.x);        // lo = out[2j], hi = out[2j+1]
    };

    __half* qrow = g_qT + (head * N_TOK + n) * DH;
    __half* krow = g_kT + (head * N_TOK + n) * DH;
    if (part == 0) {
        // q d0..11
        *reinterpret_cast<uint4*>(qrow) =
            make_uint4(h2of(a[0]), h2of(a[1]), h2of(a[2]), h2of(a[3]));
        *reinterpret_cast<uint2*>(qrow + 8) = make_uint2(h2of(a[4]), h2of(a[5]));
    } else if (part == 1) {
        // q d12..15, k d0..7
        *reinterpret_cast<uint2*>(qrow + 12) = make_uint2(h2of(a[0]), h2of(a[1]));
        *reinterpret_cast<uint4*>(krow) =
            make_uint4(h2of(a[2]), h2of(a[3]), h2of(a[4]), h2of(a[5]));
    } else if (part == 2) {
        // k d8..15, v d0..3
        *reinterpret_cast<uint4*>(krow + 8) =
            make_uint4(h2of(a[0]), h2of(a[1]), h2of(a[2]), h2of(a[3]));
#pragma unroll
        for (int j = 4; j < 6; ++j) {
            float2 f = unpack2(a[j]);
            int d = 2 * (j - 4);
            g_v[(head * DH + d) * N_TOK + n]     = __float2half(f.x);
            g_v[(head * DH + d + 1) * N_TOK + n] = __float2half(f.y);
        }
    } else {
        // v d4..15
#pragma unroll
        for (int j = 0; j < 6; ++j) {
            float2 f = unpack2(a[j]);
            int d = 4 + 2 * j;
            g_v[(head * DH + d) * N_TOK + n]     = __float2half(f.x);
            g_v[(head * DH + d + 1) * N_TOK + n] = __float2half(f.y);
        }
    }
}

// ---------------- Kernel 2: fp16 mma flash attention, split-KV x4 ----------------
// grid 1024: head = bx>>7, rowblock = (bx>>2)&31, split = bx&3.
// CTA 128 thr = 4 warps x 32 rows. Ksm [tok][d] stride 12, Vsm [d][tok] stride 76.
#define KSTR 12
#define VSTR 76
#define COLS_PER_SPLIT (N_TOK / NSPLIT)

__global__ void __launch_bounds__(128, 6) attn_kernel() {
    __shared__ __align__(16) uint32_t Ksm[128 * KSTR];   // 6144 B
    __shared__ __align__(16) uint32_t Vsm[16 * VSTR];    // 4864 B

    const int tid  = threadIdx.x;
    const int w    = tid >> 5;
    const int lane = tid & 31;
    const int gr   = lane >> 2;
    const int tg   = lane & 3;
    const int head  = blockIdx.x >> 7;
    const int r0    = ((blockIdx.x >> 2) & 31) * 128 + w * 32;
    const int split = blockIdx.x & 3;
    const int jt0   = split * COLS_PER_SPLIT;

    uint32_t qa[2][4];
    const __half* qbase = g_qT + head * N_TOK * DH;
#pragma unroll
    for (int m = 0; m < 2; ++m) {
        int rA = r0 + m * 16 + gr;
        qa[m][0] = *reinterpret_cast<const uint32_t*>(qbase + rA * DH + 2 * tg);
        qa[m][1] = *reinterpret_cast<const uint32_t*>(qbase + (rA + 8) * DH + 2 * tg);
        qa[m][2] = *reinterpret_cast<const uint32_t*>(qbase + rA * DH + 2 * tg + 8);
        qa[m][3] = *reinterpret_cast<const uint32_t*>(qbase + (rA + 8) * DH + 2 * tg + 8);
    }

    float o[2][2][4];
    float dn[2][4];
#pragma unroll
    for (int m = 0; m < 2; ++m)
#pragma unroll
        for (int i = 0; i < 4; ++i) { o[m][0][i] = 0.f; o[m][1][i] = 0.f; dn[m][i] = 0.f; }
    const uint32_t ones = (gr == 0) ? 0x3C003C00u : 0u;

    for (int jt = jt0; jt < jt0 + COLS_PER_SPLIT; jt += 128) {
        __syncthreads();
        {   // stage K: thread -> one token (32B)
            const uint4* s = reinterpret_cast<const uint4*>(g_kT + (head * N_TOK + jt + tid) * DH);
            uint4 k0 = s[0], k1 = s[1];
            *reinterpret_cast<uint4*>(&Ksm[tid * KSTR])     = k0;
            *reinterpret_cast<uint4*>(&Ksm[tid * KSTR + 4]) = k1;
        }
        {   // stage V
            int d = tid >> 3, ch = tid & 7;
            const uint4* s = reinterpret_cast<const uint4*>(g_v + (head * DH + d) * N_TOK + jt + ch * 16);
            uint4 v0 = s[0], v1 = s[1];
            *reinterpret_cast<uint4*>(&Vsm[d * VSTR + ch * 8])     = v0;
            *reinterpret_cast<uint4*>(&Vsm[d * VSTR + ch * 8 + 4]) = v1;
        }
        __syncthreads();

#pragma unroll 2
        for (int s = 0; s < 8; ++s) {
            uint32_t pa[2][4];
#pragma unroll
            for (int hlf = 0; hlf < 2; ++hlf) {
                const int nt = 2 * s + hlf;
                const uint32_t b0 = Ksm[(nt * 8 + gr) * KSTR + tg];
                const uint32_t b1 = Ksm[(nt * 8 + gr) * KSTR + tg + 4];
#pragma unroll
                for (int m = 0; m < 2; ++m) {
                    float c0 = 0.f, c1 = 0.f, c2 = 0.f, c3 = 0.f;
                    hmma(c0, c1, c2, c3, qa[m][0], qa[m][1], qa[m][2], qa[m][3], b0, b1);
                    pa[m][hlf * 2]     = ex2_h2(cvt_h2(c1, c0));
                    pa[m][hlf * 2 + 1] = ex2_h2(cvt_h2(c3, c2));
                }
            }
#pragma unroll
            for (int m = 0; m < 2; ++m)
                hmma(dn[m][0], dn[m][1], dn[m][2], dn[m][3],
                     pa[m][0], pa[m][1], pa[m][2], pa[m][3], ones, ones);
#pragma unroll
            for (int nb = 0; nb < 2; ++nb) {
                const uint32_t b0 = Vsm[(nb * 8 + gr) * VSTR + s * 8 + tg];
                const uint32_t b1 = Vsm[(nb * 8 + gr) * VSTR + s * 8 + tg + 4];
#pragma unroll
                for (int m = 0; m < 2; ++m)
                    hmma(o[m][nb][0], o[m][nb][1], o[m][nb][2], o[m][nb][3],
                         pa[m][0], pa[m][1], pa[m][2], pa[m][3], b0, b1);
            }
        }
    }

    // write partials (no divide)
#pragma unroll
    for (int m = 0; m < 2; ++m) {
        const int rA = r0 + m * 16 + gr;
        if (tg == 0) {
            g_pden[split][head][rA]     = dn[m][0];
            g_pden[split][head][rA + 8] = dn[m][2];
        }
#pragma unroll
        for (int nb = 0; nb < 2; ++nb) {
            const int d0 = nb * 8 + 2 * tg;
            g_pnum[split][head][d0][rA]         = o[m][nb][0];
            g_pnum[split][head][d0 + 1][rA]     = o[m][nb][1];
            g_pnum[split][head][d0][rA + 8]     = o[m][nb][2];
            g_pnum[split][head][d0 + 1][rA + 8] = o[m][nb][3];
        }
    }
}

// ---------------- Kernel 3: combine splits ----------------
__global__ void __launch_bounds__(256) combine_kernel(float* __restrict__ out) {
    int g = blockIdx.x * 256 + threadIdx.x;        // 131072 float4 items
    int h = g / (DH * 1024);
    int rem = g % (DH * 1024);
    int d = rem / 1024;
    int t = (rem % 1024) * 4;

    float4 ns = make_float4(0.f, 0.f, 0.f, 0.f);
    float4 es = make_float4(0.f, 0.f, 0.f, 0.f);
#pragma unroll
    for (int sp = 0; sp < NSPLIT; ++sp) {
        float4 nv = *reinterpret_cast<const float4*>(&g_pnum[sp][h][d][t]);
        float4 ev = *reinterpret_cast<const float4*>(&g_pden[sp][h][t]);
        ns.x += nv.x; ns.y += nv.y; ns.z += nv.z; ns.w += nv.w;
        es.x += ev.x; es.y += ev.y; es.z += ev.z; es.w += ev.w;
    }
    float4 r = make_float4(ns.x / es.x, ns.y / es.y, ns.z / es.z, ns.w / es.w);
    *reinterpret_cast<float4*>(&out[(h * DH + d) * N_TOK + t]) = r;
}

extern "C" void kernel_launch(void* const* d_in, const int* in_sizes, int n_in,
                              void* d_out, int out_size) {
    const float* x = (const float*)d_in[0];   // (1,128,64,64) -> [c][n]
    const float* W = (const float*)d_in[1];   // (384,128)
    float* out = (float*)d_out;

    qkv_proj_kernel<<<dim3(32, 32), 128>>>(x, W);
    attn_kernel<<<NH * 32 * NSPLIT, 128>>>();                 // 1024 CTAs
    combine_kernel<<<(NH * DH * 1024) / 256, 256>>>(out);     // 512 CTAs
}

// round 11
// speedup vs baseline: 1.2266x; 1.2266x over previous
#include <cuda_runtime.h>
#include <cuda_fp16.h>
#include <cstdint>

#define N_TOK 4096
#define NH 8
#define DH 16
#define DM 128
#define NSPLIT 4
// (1/sqrt(128)) * log2(e): softmax in exp2 domain
#define QSCL 0.12751743f

// fp16 scratch written by projection
__device__ __half g_qT[NH * N_TOK * DH];   // [head][tok][d]  (q, pre-scaled)
__device__ __half g_kT[NH * N_TOK * DH];   // [head][tok][d]
__device__ __half g_v [NH * DH * N_TOK];   // [head*16+d][tok]
// split-KV partials
__device__ float g_pnum[NSPLIT][NH][DH][N_TOK];   // 8 MB
__device__ float g_pden[NSPLIT][NH][N_TOK];       // 512 KB

// ---------------- helpers ----------------
__device__ __forceinline__ uint32_t cvt_h2(float hi, float lo) {
    uint32_t d;
    asm("cvt.rn.f16x2.f32 %0, %1, %2;" : "=r"(d) : "f"(hi), "f"(lo));
    return d;
}
__device__ __forceinline__ uint32_t ex2_h2(uint32_t a) {
    uint32_t d;
    asm("ex2.approx.f16x2 %0, %1;" : "=r"(d) : "r"(a));
    return d;
}
__device__ __forceinline__ void hmma(float& c0, float& c1, float& c2, float& c3,
                                     uint32_t a0, uint32_t a1, uint32_t a2, uint32_t a3,
                                     uint32_t b0, uint32_t b1) {
    asm volatile("mma.sync.aligned.m16n8k16.row.col.f32.f16.f16.f32 "
                 "{%0,%1,%2,%3}, {%4,%5,%6,%7}, {%8,%9}, {%0,%1,%2,%3};"
                 : "+f"(c0), "+f"(c1), "+f"(c2), "+f"(c3)
                 : "r"(a0), "r"(a1), "r"(a2), "r"(a3), "r"(b0), "r"(b1));
}
__device__ __forceinline__ void ldsm4t(uint32_t& r0, uint32_t& r1,
                                       uint32_t& r2, uint32_t& r3, uint32_t addr) {
    asm volatile("ldmatrix.sync.aligned.m8n8.x4.trans.shared.b16 {%0,%1,%2,%3}, [%4];"
                 : "=r"(r0), "=r"(r1), "=r"(r2), "=r"(r3) : "r"(addr));
}

// ---------------- Kernel 1: tensor-core QKV projection ----------------
// grid (6, 64): bx = 64-row M tile (4 warps x m16), by = 64-token tile.
// Each warp's 16 rows are exactly one of {q,k,v} of one head (48 = 3*16).
// x staged to smem fp16 [c][n] (stride 72); ldmatrix.trans builds B-frags.
#define XSTR 72

__global__ void __launch_bounds__(128) qkv_proj_kernel(const float* __restrict__ x,
                                                       const float* __restrict__ W) {
    __shared__ __align__(16) __half xsm[DM * XSTR];   // 18 KB
    const int tid  = threadIdx.x;
    const int w    = tid >> 5;
    const int lane = tid & 31;
    const int gr   = lane >> 2;
    const int tg   = lane & 3;

    const int nt0   = blockIdx.y * 64;            // token base
    const int group = blockIdx.x * 4 + w;         // 0..23
    const int head  = group / 3;
    const int type  = group % 3;                  // 0=q 1=k 2=v
    const int ob    = group * 16;                 // W row base

    // A-fragments from W (fp32 -> fp16), q rows pre-scaled
    const float scl = (type == 0) ? QSCL : 1.f;
    uint32_t af[8][4];
    const float* Wr0 = W + (ob + gr) * DM;
    const float* Wr1 = W + (ob + gr + 8) * DM;
#pragma unroll
    for (int ks = 0; ks < 8; ++ks) {
        const int c0 = ks * 16 + 2 * tg;
        float2 w00 = *reinterpret_cast<const float2*>(Wr0 + c0);
        float2 w10 = *reinterpret_cast<const float2*>(Wr1 + c0);
        float2 w01 = *reinterpret_cast<const float2*>(Wr0 + c0 + 8);
        float2 w11 = *reinterpret_cast<const float2*>(Wr1 + c0 + 8);
        af[ks][0] = cvt_h2(w00.y * scl, w00.x * scl);
        af[ks][1] = cvt_h2(w10.y * scl, w10.x * scl);
        af[ks][2] = cvt_h2(w01.y * scl, w01.x * scl);
        af[ks][3] = cvt_h2(w11.y * scl, w11.x * scl);
    }

    // stage x tile: thread = one channel row, 64 tokens, fp32 -> fp16
    {
        const float4* xr = reinterpret_cast<const float4*>(x + tid * N_TOK + nt0);
#pragma unroll
        for (int j = 0; j < 16; ++j) {
            float4 v = xr[j];
            *reinterpret_cast<uint2*>(&xsm[tid * XSTR + 4 * j]) =
                make_uint2(cvt_h2(v.y, v.x), cvt_h2(v.w, v.z));
        }
    }
    __syncthreads();

    float acc[8][4];
#pragma unroll
    for (int nb = 0; nb < 8; ++nb)
#pragma unroll
        for (int i = 0; i < 4; ++i) acc[nb][i] = 0.f;

    const uint32_t lmbase =
        (uint32_t)__cvta_generic_to_shared(xsm) +
        ((lane & 15) * XSTR + (lane >> 4) * 8) * 2;

#pragma unroll
    for (int ks = 0; ks < 8; ++ks) {
        uint32_t b[8][2];
#pragma unroll
        for (int nc = 0; nc < 4; ++nc) {
            const uint32_t a = lmbase + (ks * 16 * XSTR + nc * 16) * 2;
            ldsm4t(b[2 * nc][0], b[2 * nc][1], b[2 * nc + 1][0], b[2 * nc + 1][1], a);
        }
#pragma unroll
        for (int nb = 0; nb < 8; ++nb)
            hmma(acc[nb][0], acc[nb][1], acc[nb][2], acc[nb][3],
                 af[ks][0], af[ks][1], af[ks][2], af[ks][3], b[nb][0], b[nb][1]);
    }

    // epilogue
    if (type < 2) {
        __half* base = (type == 0 ? g_qT : g_kT) + head * N_TOK * DH;
#pragma unroll
        for (int nb = 0; nb < 8; ++nb) {
            const int t0 = nt0 + nb * 8 + 2 * tg;
            base[t0 * DH + gr]           = __float2half(acc[nb][0]);
            base[(t0 + 1) * DH + gr]     = __float2half(acc[nb][1]);
            base[t0 * DH + gr + 8]       = __float2half(acc[nb][2]);
            base[(t0 + 1) * DH + gr + 8] = __float2half(acc[nb][3]);
        }
    } else {
#pragma unroll
        for (int nb = 0; nb < 8; ++nb) {
            const int t0 = nt0 + nb * 8 + 2 * tg;
            *reinterpret_cast<uint32_t*>(&g_v[(head * DH + gr) * N_TOK + t0]) =
                cvt_h2(acc[nb][1], acc[nb][0]);
            *reinterpret_cast<uint32_t*>(&g_v[(head * DH + gr + 8) * N_TOK + t0]) =
                cvt_h2(acc[nb][3], acc[nb][2]);
        }
    }
}

// ---------------- Kernel 2: fp16 mma flash attention, split-KV x4 ----------------
// grid 1024: head = bx>>7, rowblock = (bx>>2)&31, split = bx&3.
// CTA 128 thr = 4 warps x 32 rows. Ksm [tok][d] stride 12, Vsm [d][tok] stride 76.
#define KSTR 12
#define VSTR 76
#define COLS_PER_SPLIT (N_TOK / NSPLIT)

__global__ void __launch_bounds__(128, 6) attn_kernel() {
    __shared__ __align__(16) uint32_t Ksm[128 * KSTR];   // 6144 B
    __shared__ __align__(16) uint32_t Vsm[16 * VSTR];    // 4864 B

    const int tid  = threadIdx.x;
    const int w    = tid >> 5;
    const int lane = tid & 31;
    const int gr   = lane >> 2;
    const int tg   = lane & 3;
    const int head  = blockIdx.x >> 7;
    const int r0    = ((blockIdx.x >> 2) & 31) * 128 + w * 32;
    const int split = blockIdx.x & 3;
    const int jt0   = split * COLS_PER_SPLIT;

    uint32_t qa[2][4];
    const __half* qbase = g_qT + head * N_TOK * DH;
#pragma unroll
    for (int m = 0; m < 2; ++m) {
        int rA = r0 + m * 16 + gr;
        qa[m][0] = *reinterpret_cast<const uint32_t*>(qbase + rA * DH + 2 * tg);
        qa[m][1] = *reinterpret_cast<const uint32_t*>(qbase + (rA + 8) * DH + 2 * tg);
        qa[m][2] = *reinterpret_cast<const uint32_t*>(qbase + rA * DH + 2 * tg + 8);
        qa[m][3] = *reinterpret_cast<const uint32_t*>(qbase + (rA + 8) * DH + 2 * tg + 8);
    }

    float o[2][2][4];
    float dn[2][4];
#pragma unroll
    for (int m = 0; m < 2; ++m)
#pragma unroll
        for (int i = 0; i < 4; ++i) { o[m][0][i] = 0.f; o[m][1][i] = 0.f; dn[m][i] = 0.f; }
    const uint32_t ones = (gr == 0) ? 0x3C003C00u : 0u;

    for (int jt = jt0; jt < jt0 + COLS_PER_SPLIT; jt += 128) {
        __syncthreads();
        {   // stage K: thread -> one token (32B)
            const uint4* s = reinterpret_cast<const uint4*>(g_kT + (head * N_TOK + jt + tid) * DH);
            uint4 k0 = s[0], k1 = s[1];
            *reinterpret_cast<uint4*>(&Ksm[tid * KSTR])     = k0;
            *reinterpret_cast<uint4*>(&Ksm[tid * KSTR + 4]) = k1;
        }
        {   // stage V
            int d = tid >> 3, ch = tid & 7;
            const uint4* s = reinterpret_cast<const uint4*>(g_v + (head * DH + d) * N_TOK + jt + ch * 16);
            uint4 v0 = s[0], v1 = s[1];
            *reinterpret_cast<uint4*>(&Vsm[d * VSTR + ch * 8])     = v0;
            *reinterpret_cast<uint4*>(&Vsm[d * VSTR + ch * 8 + 4]) = v1;
        }
        __syncthreads();

#pragma unroll 2
        for (int s = 0; s < 8; ++s) {
            uint32_t pa[2][4];
#pragma unroll
            for (int hlf = 0; hlf < 2; ++hlf) {
                const int nt = 2 * s + hlf;
                const uint32_t b0 = Ksm[(nt * 8 + gr) * KSTR + tg];
                const uint32_t b1 = Ksm[(nt * 8 + gr) * KSTR + tg + 4];
#pragma unroll
                for (int m = 0; m < 2; ++m) {
                    float c0 = 0.f, c1 = 0.f, c2 = 0.f, c3 = 0.f;
                    hmma(c0, c1, c2, c3, qa[m][0], qa[m][1], qa[m][2], qa[m][3], b0, b1);
                    pa[m][hlf * 2]     = ex2_h2(cvt_h2(c1, c0));
                    pa[m][hlf * 2 + 1] = ex2_h2(cvt_h2(c3, c2));
                }
            }
#pragma unroll
            for (int m = 0; m < 2; ++m)
                hmma(dn[m][0], dn[m][1], dn[m][2], dn[m][3],
                     pa[m][0], pa[m][1], pa[m][2], pa[m][3], ones, ones);
#pragma unroll
            for (int nb = 0; nb < 2; ++nb) {
                const uint32_t b0 = Vsm[(nb * 8 + gr) * VSTR + s * 8 + tg];
                const uint32_t b1 = Vsm[(nb * 8 + gr) * VSTR + s * 8 + tg + 4];
#pragma unroll
                for (int m = 0; m < 2; ++m)
                    hmma(o[m][nb][0], o[m][nb][1], o[m][nb][2], o[m][nb][3],
                         pa[m][0], pa[m][1], pa[m][2], pa[m][3], b0, b1);
            }
        }
    }

    // write partials (no divide)
#pragma unroll
    for (int m = 0; m < 2; ++m) {
        const int rA = r0 + m * 16 + gr;
        if (tg == 0) {
            g_pden[split][head][rA]     = dn[m][0];
            g_pden[split][head][rA + 8] = dn[m][2];
        }
#pragma unroll
        for (int nb = 0; nb < 2; ++nb) {
            const int d0 = nb * 8 + 2 * tg;
            g_pnum[split][head][d0][rA]         = o[m][nb][0];
            g_pnum[split][head][d0 + 1][rA]     = o[m][nb][1];
            g_pnum[split][head][d0][rA + 8]     = o[m][nb][2];
            g_pnum[split][head][d0 + 1][rA + 8] = o[m][nb][3];
        }
    }
}

// ---------------- Kernel 3: combine splits ----------------
__global__ void __launch_bounds__(256) combine_kernel(float* __restrict__ out) {
    int g = blockIdx.x * 256 + threadIdx.x;        // 131072 float4 items
    int h = g / (DH * 1024);
    int rem = g % (DH * 1024);
    int d = rem / 1024;
    int t = (rem % 1024) * 4;

    float4 ns = make_float4(0.f, 0.f, 0.f, 0.f);
    float4 es = make_float4(0.f, 0.f, 0.f, 0.f);
#pragma unroll
    for (int sp = 0; sp < NSPLIT; ++sp) {
        float4 nv = *reinterpret_cast<const float4*>(&g_pnum[sp][h][d][t]);
        float4 ev = *reinterpret_cast<const float4*>(&g_pden[sp][h][t]);
        ns.x += nv.x; ns.y += nv.y; ns.z += nv.z; ns.w += nv.w;
        es.x += ev.x; es.y += ev.y; es.z += ev.z; es.w += ev.w;
    }
    float4 r = make_float4(ns.x / es.x, ns.y / es.y, ns.z / es.z, ns.w / es.w);
    *reinterpret_cast<float4*>(&out[(h * DH + d) * N_TOK + t]) = r;
}

extern "C" void kernel_launch(void* const* d_in, const int* in_sizes, int n_in,
                              void* d_out, int out_size) {
    const float* x = (const float*)d_in[0];   // (1,128,64,64) -> [c][n]
    const float* W = (const float*)d_in[1];   // (384,128)
    float* out = (float*)d_out;

    qkv_proj_kernel<<<dim3(6, 64), 128>>>(x, W);
    attn_kernel<<<NH * 32 * NSPLIT, 128>>>();                 // 1024 CTAs
    combine_kernel<<<(NH * DH * 1024) / 256, 256>>>(out);     // 512 CTAs
}